// round 10
// baseline (speedup 1.0000x reference)
#include <cuda_runtime.h>
#include <cuda_bf16.h>
#include <math.h>

#define BZ 32
#define SZ 128
#define HZ 768
#define MH_ 6
#define KK 4
#define NQ 8     // octants per batch
#define ST 16    // span starts per block

__constant__ float c_inv[8] = {1.f, 1.f/2.f, 1.f/3.f, 1.f/4.f, 1.f/5.f, 1.f/6.f, 1.f/7.f, 1.f/8.f};

__device__ unsigned long long g_cand[BZ * 2 * NQ * 4];  // [b][type][oct][4]
__device__ unsigned int g_tick[BZ];                     // zero-init; elected resets

#define CE(x, y) { unsigned long long _a = (x), _b = (y); (x) = _a > _b ? _a : _b; (y) = _a > _b ? _b : _a; }

// Butterfly merge of per-lane sorted-4 desc lists. OFF0=16: warp-wide; OFF0=8: per 16-lane half.
#define MERGE4(k0, k1, k2, k3, OFF0)                                           \
    _Pragma("unroll")                                                          \
    for (int off = (OFF0); off; off >>= 1) {                                   \
        unsigned long long o0 = __shfl_xor_sync(0xFFFFFFFFu, k0, off);         \
        unsigned long long o1 = __shfl_xor_sync(0xFFFFFFFFu, k1, off);         \
        unsigned long long o2 = __shfl_xor_sync(0xFFFFFFFFu, k2, off);         \
        unsigned long long o3 = __shfl_xor_sync(0xFFFFFFFFu, k3, off);         \
        unsigned long long c0 = k0 > o3 ? k0 : o3;                             \
        unsigned long long c1 = k1 > o2 ? k1 : o2;                             \
        unsigned long long c2 = k2 > o1 ? k2 : o1;                             \
        unsigned long long c3 = k3 > o0 ? k3 : o0;                             \
        CE(c0, c2); CE(c1, c3); CE(c0, c1); CE(c2, c3);                        \
        k0 = c0; k1 = c1; k2 = c2; k3 = c3;                                    \
    }

// out layout (floats): implicit[0,512) explicit[512,2560) hs[2560,35328) ts[35328,68096)

__global__ __launch_bounds__(256, 2) void k_all(
    const float* __restrict__ emb,
    const int* __restrict__ mask,
    const float* __restrict__ wh,
    const float* __restrict__ bh_,
    const float* __restrict__ wt,
    const float* __restrict__ bt_,
    const float* __restrict__ wi,
    const float* __restrict__ bi,
    const float* __restrict__ we,
    const float* __restrict__ be,
    float* __restrict__ out)
{
    __shared__ __align__(16) float swh[HZ];   // 3 KB
    __shared__ __align__(16) float swt[HZ];   // 3 KB
    __shared__ float sdot[2][24];             // [0]=target(wt), [1]=holder(wh)
    __shared__ unsigned long long cand[2][32];
    __shared__ float topv[2][KK];
    __shared__ int   topi[2][KK];
    __shared__ float partial[8][8];
    __shared__ float sbias[8];                // 0-3: bi, 4-7: be
    __shared__ float s_bh, s_bt;
    __shared__ int s_flag, s_len;

    const int b = blockIdx.x, q = blockIdx.y;
    const int tid = threadIdx.x;
    const int warp = tid >> 5, lane = tid & 31;
    const float* eb = emb + (size_t)b * SZ * HZ;

    // ---- stage wh/wt to smem; scalars; mask length (warp 7) ----
    {
        float4* swh4 = (float4*)swh;
        float4* swt4 = (float4*)swt;
        for (int j = tid; j < 384; j += 256) {
            if (j < 192) swh4[j] = ((const float4*)wh)[j];
            else         swt4[j - 192] = ((const float4*)wt)[j - 192];
        }
        if (tid == 0) s_flag = 0;
        if (tid < 4)            sbias[tid] = bi[tid];
        else if (tid < 8)       sbias[tid] = be[tid - 4];
        if (tid == 8)  s_bh = bh_[0];
        if (tid == 9)  s_bt = bt_[0];
        if (warp == 7) {
            int4 mv = ((const int4*)(mask + b * SZ))[lane];
            int v = mv.x + mv.y + mv.z + mv.w;
#pragma unroll
            for (int off = 16; off; off >>= 1) v += __shfl_xor_sync(0xFFFFFFFFu, v, off);
            if (lane == 0) s_len = v;
        }
    }
    __syncthreads();

    // ---- phase A: row dots, local rows 0..22 (8 warps x 3 rows) ----
    {
        const int lr0 = warp * 3;
        float ah[3] = {0.f,0.f,0.f}, at[3] = {0.f,0.f,0.f};
        const float4* swh4 = (const float4*)swh;
        const float4* swt4 = (const float4*)swt;
#pragma unroll
        for (int r = 0; r < 3; r++) {
            int gr = q * ST + lr0 + r;
            if (lr0 + r < 23 && gr < SZ) {
                const float4* rp = (const float4*)(eb + (size_t)gr * HZ);
                float4 v[6];
#pragma unroll
                for (int i = 0; i < 6; i++) v[i] = rp[lane + 32 * i];
#pragma unroll
                for (int i = 0; i < 6; i++) {
                    float4 wv = swh4[lane + 32 * i];
                    float4 tv = swt4[lane + 32 * i];
                    ah[r] += v[i].x * wv.x + v[i].y * wv.y
                           + v[i].z * wv.z + v[i].w * wv.w;
                    at[r] += v[i].x * tv.x + v[i].y * tv.y
                           + v[i].z * tv.z + v[i].w * tv.w;
                }
            }
        }
#pragma unroll
        for (int off = 16; off; off >>= 1) {
#pragma unroll
            for (int r = 0; r < 3; r++) {
                ah[r] += __shfl_xor_sync(0xFFFFFFFFu, ah[r], off);
                at[r] += __shfl_xor_sync(0xFFFFFFFFu, at[r], off);
            }
        }
        if (lane == 0) {
#pragma unroll
            for (int r = 0; r < 3; r++) {
                sdot[0][lr0 + r] = at[r];
                sdot[1][lr0 + r] = ah[r];
            }
        }
    }
    __syncthreads();

    // ---- scores: warp = width m; lane halves = type; 16 starts ----
    {
        const int m = warp;                 // width index 0..7
        const int half = lane >> 4;         // 0=target, 1=holder
        const int sl = lane & 15;           // local start
        const int sg = q * ST + sl;
        const int gidx = m * SZ + sg;
        float s = 0.f;
        for (int r = 0; r <= m; r++) s += sdot[half][sl + r];
        const int len = s_len;
        bool valid = ((sg + m) < len) && (half == 0 || m < MH_);
        float bias = half ? s_bh : s_bt;
        float v = valid ? 1.f / (1.f + __expf(-(s * c_inv[m] + bias))) : -1.f;
        // half0 -> ts @35328, half1 -> hs @2560
        out[(half ? 2560 : 35328) + (size_t)b * 1024 + gidx] = v;

        unsigned u = __float_as_uint(v);
        u = (u & 0x80000000u) ? ~u : (u | 0x80000000u);
        unsigned long long k0 = ((unsigned long long)u << 32) | (unsigned)(0xFFFFFFFFu - gidx);
        unsigned long long k1 = 0ull, k2 = 0ull, k3 = 0ull;
        MERGE4(k0, k1, k2, k3, 8);          // within 16-lane half
        if ((lane & 15) == 0) {
            cand[half][m * 4 + 0] = k0; cand[half][m * 4 + 1] = k1;
            cand[half][m * 4 + 2] = k2; cand[half][m * 4 + 3] = k3;
        }
    }
    __syncthreads();

    // ---- block merge 32 -> 4 (warp0 targets, warp1 holders) -> g_cand ----
    if (warp < 2) {
        unsigned long long k0 = cand[warp][lane], k1 = 0ull, k2 = 0ull, k3 = 0ull;
        MERGE4(k0, k1, k2, k3, 16);
        if (lane == 0) {
            unsigned long long* dst = &g_cand[((b * 2 + warp) * NQ + q) * 4];
            dst[0] = k0; dst[1] = k1; dst[2] = k2; dst[3] = k3;
        }
    }

    // ---- election: 8th arriving block of this batch runs the tail ----
    __threadfence();
    __syncthreads();
    if (tid == 0) {
        unsigned old = atomicAdd(&g_tick[b], 1u);
        if (old == (NQ - 1)) s_flag = 1;
    }
    __syncthreads();
    if (!s_flag) return;
    if (tid == 0) g_tick[b] = 0;
    __threadfence();

    // ================= Tail (one block per batch) =========================
    // merge NQ*4 = 32 candidates per type
    if (warp < 2) {
        unsigned long long k0 = g_cand[(b * 2 + warp) * (NQ * 4) + lane];
        unsigned long long k1 = 0ull, k2 = 0ull, k3 = 0ull;
        MERGE4(k0, k1, k2, k3, 16);
        if (lane == 0) {
            unsigned long long ks[4] = {k0, k1, k2, k3};
#pragma unroll
            for (int k = 0; k < KK; k++) {
                unsigned hi = (unsigned)(ks[k] >> 32);
                unsigned lo = (unsigned)ks[k];
                float v = (hi & 0x80000000u) ? __uint_as_float(hi ^ 0x80000000u)
                                             : __uint_as_float(~hi);
                topv[warp][k] = v;
                topi[warp][k] = (int)(0xFFFFFFFFu - lo);
            }
        }
    }
    __syncthreads();

    // rep dots: 1 warp per selected span (warps 0-3 target, 4-7 holder)
    {
        const int type = warp >> 2;
        const int k = warp & 3;
        const int idx = topi[type][k];
        const bool valid = topv[type][k] > 0.f;
        const int m = idx >> 7, s = idx & 127;
        const float invw = c_inv[m];
        const float4* wi4 = (const float4*)wi;
        const float4* we4 = (const float4*)we;

        float acc[8] = {0.f,0.f,0.f,0.f,0.f,0.f,0.f,0.f};
        if (valid) {
            float4 sum[6];
#pragma unroll
            for (int i = 0; i < 6; i++) sum[i] = make_float4(0.f,0.f,0.f,0.f);
#pragma unroll
            for (int r = 0; r < 8; r++) {
                if (r <= m) {
                    const float4* rp = (const float4*)(eb + (size_t)(s + r) * HZ);
#pragma unroll
                    for (int i = 0; i < 6; i++) {
                        float4 a = rp[lane + 32 * i];
                        sum[i].x += a.x; sum[i].y += a.y;
                        sum[i].z += a.z; sum[i].w += a.w;
                    }
                }
            }
#pragma unroll
            for (int i = 0; i < 6; i++) {
                int h4 = lane + 32 * i;
                float sv[4] = {sum[i].x * invw, sum[i].y * invw,
                               sum[i].z * invw, sum[i].w * invw};
#pragma unroll
                for (int j = 0; j < 4; j++) {
                    int f = 4 * h4 + j;
                    if (type == 0) {
                        float4 wv = wi4[f];
                        acc[0] += sv[j] * wv.x; acc[1] += sv[j] * wv.y;
                        acc[2] += sv[j] * wv.z; acc[3] += sv[j] * wv.w;
                        float4 ev = we4[HZ + f];
                        acc[4] += sv[j] * ev.x; acc[5] += sv[j] * ev.y;
                        acc[6] += sv[j] * ev.z; acc[7] += sv[j] * ev.w;
                    } else {
                        float4 ev = we4[f];
                        acc[0] += sv[j] * ev.x; acc[1] += sv[j] * ev.y;
                        acc[2] += sv[j] * ev.z; acc[3] += sv[j] * ev.w;
                    }
                }
            }
        }
#pragma unroll
        for (int off = 16; off; off >>= 1)
#pragma unroll
            for (int j = 0; j < 8; j++)
                acc[j] += __shfl_xor_sync(0xFFFFFFFFu, acc[j], off);
        if (lane == 0) {
#pragma unroll
            for (int j = 0; j < 8; j++) partial[warp][j] = acc[j];
        }
    }
    __syncthreads();

    // logits
    if (tid < 64) {
        int k = tid >> 4, i = (tid >> 2) & 3, j = tid & 3;
        bool pv = (topv[1][k] > 0.f) && (topv[0][i] > 0.f);
        float val = sbias[4 + j];
        if (pv) val += partial[4 + k][j] + partial[i][4 + j];
        out[512 + (size_t)b * 64 + tid] = val;
    } else if (tid < 80) {
        int t2 = tid - 64;
        int i = t2 >> 2, j = t2 & 3;
        float val = sbias[j];
        if (topv[0][i] > 0.f) val += partial[i][j];
        out[(size_t)b * 16 + t2] = val;
    }
}

extern "C" void kernel_launch(void* const* d_in, const int* in_sizes, int n_in,
                              void* d_out, int out_size)
{
    const float* emb = (const float*)d_in[0];
    const int*   msk = (const int*)d_in[1];
    const float* wh  = (const float*)d_in[2];
    const float* bh  = (const float*)d_in[3];
    const float* wt  = (const float*)d_in[4];
    const float* bt  = (const float*)d_in[5];
    const float* wi  = (const float*)d_in[6];
    const float* bi  = (const float*)d_in[7];
    const float* we  = (const float*)d_in[8];
    const float* be  = (const float*)d_in[9];
    float* out = (float*)d_out;

    dim3 g(BZ, NQ, 1);
    k_all<<<g, 256>>>(emb, msk, wh, bh, wt, bt, wi, bi, we, be, out);
}

// round 11
// speedup vs baseline: 1.0911x; 1.0911x over previous
#include <cuda_runtime.h>
#include <cuda_bf16.h>
#include <math.h>

#define BZ 32
#define SZ 128
#define HZ 768
#define MH_ 6
#define KK 4

__constant__ float c_inv[8] = {1.f, 1.f/2.f, 1.f/3.f, 1.f/4.f, 1.f/5.f, 1.f/6.f, 1.f/7.f, 1.f/8.f};

__device__ unsigned long long g_cand[BZ * 2 * 4 * 4];  // [b][type][quarter][4] packed (ordval<<32)|idx
__device__ unsigned int g_tick[BZ];                    // zero-init; elected resets

// out layout (floats): implicit[0,512) explicit[512,2560) hs[2560,35328) ts[35328,68096)

__global__ __launch_bounds__(512, 1) void k_all(
    const float* __restrict__ emb,
    const int* __restrict__ mask,
    const float* __restrict__ wh,
    const float* __restrict__ bh_,
    const float* __restrict__ wt,
    const float* __restrict__ bt_,
    const float* __restrict__ wi,
    const float* __restrict__ bi,
    const float* __restrict__ we,
    const float* __restrict__ be,
    float* __restrict__ out)
{
    __shared__ __align__(16) float swh[HZ];   // 3 KB
    __shared__ __align__(16) float swt[HZ];   // 3 KB
    __shared__ float sdot[2][40];             // [0]=target(wt), [1]=holder(wh)
    __shared__ unsigned cand_v[2][32];
    __shared__ int      cand_i[2][32];
    __shared__ float topv[2][KK];
    __shared__ int   topi[2][KK];
    __shared__ float partial[16][8];
    __shared__ float sbias[8];                // 0-3: bi, 4-7: be
    __shared__ float s_bh, s_bt;
    __shared__ int s_flag, s_len;

    const int b = blockIdx.x, q = blockIdx.y;
    const int tid = threadIdx.x;
    const int warp = tid >> 5, lane = tid & 31;
    const float* eb = emb + (size_t)b * SZ * HZ;

    // ---- stage wh/wt to smem; scalars; mask length ----
    {
        float4* swh4 = (float4*)swh;
        float4* swt4 = (float4*)swt;
        if (tid < 384) {
            if (tid < 192) swh4[tid] = ((const float4*)wh)[tid];
            else           swt4[tid - 192] = ((const float4*)wt)[tid - 192];
        }
        if (tid == 0) s_flag = 0;
        if (tid < 4)            sbias[tid] = bi[tid];
        else if (tid < 8)       sbias[tid] = be[tid - 4];
        if (tid == 8)  s_bh = bh_[0];
        if (tid == 9)  s_bt = bt_[0];
        if (warp == 13) {
            int4 mv = ((const int4*)(mask + b * SZ))[lane];
            int v = __reduce_add_sync(0xFFFFFFFFu, mv.x + mv.y + mv.z + mv.w);
            if (lane == 0) s_len = v;
        }
    }
    __syncthreads();

    // ---- phase A: row dots for local rows 0..39 (16 warps x 3 rows) ----
    {
        const int lr0 = warp * 3;
        float ah[3] = {0.f,0.f,0.f}, at[3] = {0.f,0.f,0.f};
        const float4* swh4 = (const float4*)swh;
        const float4* swt4 = (const float4*)swt;
#pragma unroll
        for (int r = 0; r < 3; r++) {
            int lr = lr0 + r;
            int gr = q * 32 + lr;
            if (lr < 40 && gr < SZ) {
                const float4* rp = (const float4*)(eb + (size_t)gr * HZ);
                float4 v[6];
#pragma unroll
                for (int i = 0; i < 6; i++) v[i] = rp[lane + 32 * i];
#pragma unroll
                for (int i = 0; i < 6; i++) {
                    float4 wv = swh4[lane + 32 * i];
                    float4 tv = swt4[lane + 32 * i];
                    ah[r] += v[i].x * wv.x + v[i].y * wv.y
                           + v[i].z * wv.z + v[i].w * wv.w;
                    at[r] += v[i].x * tv.x + v[i].y * tv.y
                           + v[i].z * tv.z + v[i].w * tv.w;
                }
            }
        }
#pragma unroll
        for (int off = 16; off; off >>= 1) {
#pragma unroll
            for (int r = 0; r < 3; r++) {
                ah[r] += __shfl_xor_sync(0xFFFFFFFFu, ah[r], off);
                at[r] += __shfl_xor_sync(0xFFFFFFFFu, at[r], off);
            }
        }
        if (lane == 0) {
#pragma unroll
            for (int r = 0; r < 3; r++) {
                int lr = lr0 + r;
                if (lr < 40) {
                    sdot[0][lr] = at[r];
                    sdot[1][lr] = ah[r];
                }
            }
        }
    }
    __syncthreads();

    // ---- scores: warp = type*8 + width; lane = local start; REDUX top-4 ----
    {
        const int type = warp >> 3;         // 0=target, 1=holder
        const int m = warp & 7;             // width index
        const int sg = q * 32 + lane;
        const int gidx = m * SZ + sg;
        float s = 0.f;
        for (int r = 0; r <= m; r++) s += sdot[type][lane + r];
        const int len = s_len;
        bool valid = ((sg + m) < len) && (type == 0 || m < MH_);
        float bias = type ? s_bh : s_bt;
        float v = valid ? 1.f / (1.f + __expf(-(s * c_inv[m] + bias))) : -1.f;
        out[(type ? 2560 : 35328) + (size_t)b * 1024 + gidx] = v;

        unsigned uv = __float_as_uint(v);
        uv = (uv & 0x80000000u) ? ~uv : (uv | 0x80000000u);   // ordered; always > 0
#pragma unroll
        for (int k = 0; k < KK; k++) {
            unsigned mx = __reduce_max_sync(0xFFFFFFFFu, uv);
            unsigned tie = __ballot_sync(0xFFFFFFFFu, uv == mx);
            if (uv == mx) {
                int wi2 = (int)__reduce_min_sync(tie, (unsigned)gidx);
                if (gidx == wi2) {
                    cand_v[type][m * 4 + k] = mx;
                    cand_i[type][m * 4 + k] = gidx;
                    uv = 0u;
                }
            }
        }
    }
    __syncthreads();

    // ---- block merge 32 -> 4 (warp0 targets, warp1 holders) -> g_cand ----
    if (warp < 2) {
        unsigned uv = cand_v[warp][lane];
        int gi = cand_i[warp][lane];
#pragma unroll
        for (int k = 0; k < KK; k++) {
            unsigned mx = __reduce_max_sync(0xFFFFFFFFu, uv);
            unsigned tie = __ballot_sync(0xFFFFFFFFu, uv == mx);
            if (uv == mx) {
                int wi2 = (int)__reduce_min_sync(tie, (unsigned)gi);
                if (gi == wi2) {
                    g_cand[((b * 2 + warp) * 4 + q) * 4 + k] =
                        ((unsigned long long)mx << 32) | (unsigned)gi;
                    uv = 0u;
                }
            }
        }
    }

    // ---- election: 4th arriving block of this batch runs the tail ----
    __threadfence();
    __syncthreads();
    if (tid == 0) {
        unsigned old = atomicAdd(&g_tick[b], 1u);
        if (old == 3u) s_flag = 1;
    }
    __syncthreads();
    if (!s_flag) return;
    if (tid == 0) g_tick[b] = 0;
    __threadfence();

    // ================= Tail (one block per batch) =========================
    // merge 16 candidates per type (REDUX rounds)
    if (warp < 2) {
        unsigned long long kk = (lane < 16) ? g_cand[(b * 2 + warp) * 16 + lane] : 0ull;
        unsigned uv = (unsigned)(kk >> 32);
        int gi = (lane < 16) ? (int)(unsigned)kk : 0x7FFFFFFF;
#pragma unroll
        for (int k = 0; k < KK; k++) {
            unsigned mx = __reduce_max_sync(0xFFFFFFFFu, uv);
            unsigned tie = __ballot_sync(0xFFFFFFFFu, uv == mx);
            if (uv == mx) {
                int wi2 = (int)__reduce_min_sync(tie, (unsigned)gi);
                if (gi == wi2) {
                    float v = (mx & 0x80000000u) ? __uint_as_float(mx ^ 0x80000000u)
                                                 : __uint_as_float(~mx);
                    topv[warp][k] = v;
                    topi[warp][k] = gi;
                    uv = 0u;
                }
            }
        }
    }
    __syncthreads();

    // rep dots: 2 warps per selected span (warps 0-7 target, 8-15 holder)
    {
        const int type = warp >> 3;
        const int span = (warp >> 1) & 3;
        const int half = warp & 1;
        const int idx = topi[type][span];
        const bool valid = topv[type][span] > 0.f;
        const int m = idx >> 7, s = idx & 127;
        const float invw = c_inv[m];
        const float4* wi4 = (const float4*)wi;
        const float4* we4 = (const float4*)we;

        float acc[8] = {0.f,0.f,0.f,0.f,0.f,0.f,0.f,0.f};
        if (valid) {
            float4 sum[3];
#pragma unroll
            for (int i = 0; i < 3; i++) sum[i] = make_float4(0.f,0.f,0.f,0.f);
            const int c0 = lane + 96 * half;
#pragma unroll
            for (int r = 0; r < 8; r++) {
                if (r <= m) {
                    const float4* rp = (const float4*)(eb + (size_t)(s + r) * HZ);
#pragma unroll
                    for (int i = 0; i < 3; i++) {
                        float4 a = rp[c0 + 32 * i];
                        sum[i].x += a.x; sum[i].y += a.y;
                        sum[i].z += a.z; sum[i].w += a.w;
                    }
                }
            }
#pragma unroll
            for (int i = 0; i < 3; i++) {
                int h4 = c0 + 32 * i;
                float sv[4] = {sum[i].x * invw, sum[i].y * invw,
                               sum[i].z * invw, sum[i].w * invw};
#pragma unroll
                for (int j = 0; j < 4; j++) {
                    int f = 4 * h4 + j;
                    if (type == 0) {
                        float4 wv = wi4[f];
                        acc[0] += sv[j] * wv.x; acc[1] += sv[j] * wv.y;
                        acc[2] += sv[j] * wv.z; acc[3] += sv[j] * wv.w;
                        float4 ev = we4[HZ + f];
                        acc[4] += sv[j] * ev.x; acc[5] += sv[j] * ev.y;
                        acc[6] += sv[j] * ev.z; acc[7] += sv[j] * ev.w;
                    } else {
                        float4 ev = we4[f];
                        acc[0] += sv[j] * ev.x; acc[1] += sv[j] * ev.y;
                        acc[2] += sv[j] * ev.z; acc[3] += sv[j] * ev.w;
                    }
                }
            }
        }
#pragma unroll
        for (int off = 16; off; off >>= 1)
#pragma unroll
            for (int j = 0; j < 8; j++)
                acc[j] += __shfl_xor_sync(0xFFFFFFFFu, acc[j], off);
        if (lane == 0) {
#pragma unroll
            for (int j = 0; j < 8; j++) partial[warp][j] = acc[j];
        }
    }
    __syncthreads();

    // logits
    if (tid < 64) {
        int k = tid >> 4, i = (tid >> 2) & 3, j = tid & 3;
        bool pv = (topv[1][k] > 0.f) && (topv[0][i] > 0.f);
        float val = sbias[4 + j];
        if (pv) val += partial[8 + 2*k][j] + partial[8 + 2*k + 1][j]
                     + partial[2*i][4 + j] + partial[2*i + 1][4 + j];
        out[512 + (size_t)b * 64 + tid] = val;
    } else if (tid < 80) {
        int t2 = tid - 64;
        int i = t2 >> 2, j = t2 & 3;
        float val = sbias[j];
        if (topv[0][i] > 0.f) val += partial[2*i][j] + partial[2*i + 1][j];
        out[(size_t)b * 16 + t2] = val;
    }
}

extern "C" void kernel_launch(void* const* d_in, const int* in_sizes, int n_in,
                              void* d_out, int out_size)
{
    const float* emb = (const float*)d_in[0];
    const int*   msk = (const int*)d_in[1];
    const float* wh  = (const float*)d_in[2];
    const float* bh  = (const float*)d_in[3];
    const float* wt  = (const float*)d_in[4];
    const float* bt  = (const float*)d_in[5];
    const float* wi  = (const float*)d_in[6];
    const float* bi  = (const float*)d_in[7];
    const float* we  = (const float*)d_in[8];
    const float* be  = (const float*)d_in[9];
    float* out = (float*)d_out;

    dim3 g(BZ, 4, 1);
    k_all<<<g, 512>>>(emb, msk, wh, bh, wt, bt, wi, bi, we, be, out);
}